// round 6
// baseline (speedup 1.0000x reference)
#include <cuda_runtime.h>
#include <math.h>

#define IMAGE_W 256
#define IMAGE_H 256
#define EPS 1e-7f
#define SIGMA2 0.02f

#define B 16
#define N 64
#define C 3
#define PH 32
#define PW 32
#define TILE 32
#define PSZ (C*PH*PW)   // 3072 floats per stroke patch

// Precomputed per-stroke params
__device__ int2   g_fxy[B * N];
__device__ float4 g_w[B * N];     // (wx0, wx1, wy0/64, wy1/64)

// ---------------------------------------------------------------------------
// Kernel 1: per-stroke window origin + bilinear weights. 16 blocks x 64 thr.
// ---------------------------------------------------------------------------
__global__ void __launch_bounds__(64) params_kernel(
    const float* __restrict__ brushes)   // [B, N, 2]
{
    const int b = blockIdx.x;
    const int t = threadIdx.x;           // 0..63

    const float bx = brushes[(b * N + t) * 2 + 0];
    const float by = brushes[(b * N + t) * 2 + 1];

    float mnx = bx, mxx = bx, mny = by, mxy = by;
#pragma unroll
    for (int o = 16; o > 0; o >>= 1) {
        mnx = fminf(mnx, __shfl_xor_sync(0xffffffffu, mnx, o));
        mxx = fmaxf(mxx, __shfl_xor_sync(0xffffffffu, mxx, o));
        mny = fminf(mny, __shfl_xor_sync(0xffffffffu, mny, o));
        mxy = fmaxf(mxy, __shfl_xor_sync(0xffffffffu, mxy, o));
    }
    __shared__ float red[4][2];
    if ((t & 31) == 0) {
        const int w = t >> 5;
        red[0][w] = mnx; red[1][w] = mxx; red[2][w] = mny; red[3][w] = mxy;
    }
    __syncthreads();
    mnx = fminf(red[0][0], red[0][1]);
    mxx = fmaxf(red[1][0], red[1][1]);
    mny = fminf(red[2][0], red[2][1]);
    mxy = fmaxf(red[3][0], red[3][1]);

    const float gx = (bx - mnx) / (mxx - mnx + EPS) * (float)IMAGE_W;
    const float gy = (by - mny) / (mxy - mny + EPS) * (float)IMAGE_H;

    const float axc = gx - 15.5f;        // ux(q) = gx + q - 15.5
    const float fx0f = floorf(axc);
    const float dx = axc - fx0f;
    const float ayc = gy - 15.4f;        // uy(p) = gy + p - 15.4
    const float fy0f = floorf(ayc);
    const float dy = ayc - fy0f;

    const float gx0 = __expf(-(dx * dx) / SIGMA2);
    const float gx1 = __expf(-((1.0f - dx) * (1.0f - dx)) / SIGMA2);
    const float wx0 = gx0 / (gx0 + gx1 + EPS);
    const float wx1 = gx1 / (gx0 + gx1 + EPS);

    const float gy0 = __expf(-(dy * dy) / SIGMA2);
    const float gy1 = __expf(-((1.0f - dy) * (1.0f - dy)) / SIGMA2);
    const float s  = 1.0f / 64.0f;       // fold /N into wy
    const float wy0 = gy0 / (gy0 + gy1 + EPS) * s;
    const float wy1 = gy1 / (gy0 + gy1 + EPS) * s;

    g_fxy[b * N + t] = make_int2((int)fx0f, (int)fy0f);
    g_w[b * N + t]   = make_float4(wx0, wx1, wy0, wy1);
}

// ---------------------------------------------------------------------------
// Kernel 2: gather with explicit register double-buffered pipeline.
// One block per (batch, 32x32 tile), 512 threads; thread owns 2 rows x 3 ch.
// ---------------------------------------------------------------------------
__global__ void __launch_bounds__(512) brush_gather_kernel(
    const float* __restrict__ patches,   // [B, N, 3, 32, 32]
    float* __restrict__ out)             // [B, 3, 256, 256]
{
    const int b    = blockIdx.y;
    const int tile = blockIdx.x;         // 0..63
    const int tx0  = (tile & 7) * TILE;
    const int ty0  = (tile >> 3) * TILE;
    const int tid  = threadIdx.x;

    __shared__ int4     cmeta[N];        // fx, fy, patch offset (floats), pad
    __shared__ float4   cw[N];
    __shared__ unsigned smask[2];
    __shared__ int      s_cnt;

    // ---- build compacted survivor list ----
    int2 fxy; float4 w; bool ov = false;
    if (tid < N) {
        fxy = g_fxy[b * N + tid];
        w   = g_w[b * N + tid];
        ov  = !(fxy.x > tx0 + 31 || fxy.x + 32 < tx0 ||
                fxy.y > ty0 + 31 || fxy.y + 32 < ty0);
        const unsigned m = __ballot_sync(0xffffffffu, ov);
        if ((tid & 31) == 0) smask[tid >> 5] = m;
    }
    __syncthreads();
    if (tid < N) {
        const unsigned m0 = smask[0];
        if (ov) {
            const unsigned mym = (tid < 32) ? m0 : smask[1];
            const int pos = ((tid < 32) ? 0 : __popc(m0)) +
                            __popc(mym & ((1u << (tid & 31)) - 1u));
            cmeta[pos] = make_int4(fxy.x, fxy.y, (b * N + tid) * PSZ, 0);
            cw[pos]    = w;
        }
        if (tid == 0) s_cnt = __popc(m0) + __popc(smask[1]);
    }
    __syncthreads();
    const int cnt = s_cnt;

    const int lx    = tid & 31;
    const int g     = tid >> 5;          // 0..15
    const int x     = tx0 + lx;
    const int ybase = ty0 + g * 2;       // rows ybase, ybase+1

    float acc[C][2];
#pragma unroll
    for (int c = 0; c < C; c++) { acc[c][0] = 0.0f; acc[c][1] = 0.0f; }

    // branch-free tap load for one stroke (predicated; invalid -> 0)
    auto load_taps = [&](int sidx, float t0[9], float t1[9], float4& wt) {
        const int4 md = cmeta[sidx];
        wt = cw[sidx];
        const int i  = x - md.x;
        const int jb = ybase - md.y;
        const bool c0 = ((unsigned)i       < 32u);
        const bool c1 = ((unsigned)(i - 1) < 32u);
        const float* Pn = patches + md.z + i;
#pragma unroll
        for (int c = 0; c < C; c++) {
#pragma unroll
            for (int r = 0; r < 3; r++) {
                const int rr = jb - 1 + r;
                const bool rv = ((unsigned)rr < 32u);
                const float* a = Pn + c * (PH * PW) + rr * PW;
                t0[c * 3 + r] = (rv & c0) ? __ldg(a)     : 0.0f;
                t1[c * 3 + r] = (rv & c1) ? __ldg(a - 1) : 0.0f;
            }
        }
    };

    auto consume = [&](const float t0[9], const float t1[9], const float4 wt) {
#pragma unroll
        for (int c = 0; c < C; c++) {
            float h0 = wt.x * t0[c * 3 + 0] + wt.y * t1[c * 3 + 0];
            float h1 = wt.x * t0[c * 3 + 1] + wt.y * t1[c * 3 + 1];
            float h2 = wt.x * t0[c * 3 + 2] + wt.y * t1[c * 3 + 2];
            acc[c][0] += wt.z * h1 + wt.w * h0;
            acc[c][1] += wt.z * h2 + wt.w * h1;
        }
    };

    if (cnt > 0) {
        float ta0[9], ta1[9]; float4 wta;
        load_taps(0, ta0, ta1, wta);
        for (int s = 1; s < cnt; s++) {
            float tb0[9], tb1[9]; float4 wtb;
            load_taps(s, tb0, tb1, wtb);   // loads of s in flight...
            consume(ta0, ta1, wta);        // ...while consuming s-1
#pragma unroll
            for (int k = 0; k < 9; k++) { ta0[k] = tb0[k]; ta1[k] = tb1[k]; }
            wta = wtb;
        }
        consume(ta0, ta1, wta);
    }

    // ---- coalesced stores: [b][c][y][x] ----
#pragma unroll
    for (int c = 0; c < C; c++) {
        float* oc = out + ((size_t)(b * C + c) * IMAGE_H) * IMAGE_W;
        oc[(size_t)(ybase    ) * IMAGE_W + x] = acc[c][0];
        oc[(size_t)(ybase + 1) * IMAGE_W + x] = acc[c][1];
    }
}

extern "C" void kernel_launch(void* const* d_in, const int* in_sizes, int n_in,
                              void* d_out, int out_size)
{
    const float* brushes = (const float*)d_in[0];   // [16,64,2]
    const float* patches = (const float*)d_in[1];   // [16,64,3,32,32]
    float* out = (float*)d_out;                     // [16,3,256,256]

    params_kernel<<<B, 64>>>(brushes);
    dim3 grid(64, B);
    brush_gather_kernel<<<grid, 512>>>(patches, out);
}

// round 7
// speedup vs baseline: 1.3024x; 1.3024x over previous
#include <cuda_runtime.h>
#include <math.h>

#define IMAGE_W 256
#define IMAGE_H 256
#define EPS 1e-7f
#define SIGMA2 0.02f

#define B 16
#define N 64
#define C 3
#define PH 32
#define PW 32
#define TILE 32
#define PSZ (C*PH*PW)   // 3072 floats per stroke patch

// Fused kernel: one block per (batch, 32x32 tile), 512 threads.
// Warp 0 computes all stroke params + compacts tile survivors (1 barrier);
// then all threads gather: thread owns 1 col x 2 rows x 3 channels.
__global__ void __launch_bounds__(512) brush_kernel(
    const float* __restrict__ brushes,   // [B, N, 2]
    const float* __restrict__ patches,   // [B, N, 3, 32, 32]
    float* __restrict__ out)             // [B, 3, 256, 256]
{
    const int bt   = blockIdx.x;         // b*64 + tile
    const int b    = bt >> 6;
    const int tile = bt & 63;
    const int tx0  = (tile & 7) * TILE;
    const int ty0  = (tile >> 3) * TILE;
    const int tid  = threadIdx.x;

    __shared__ int4   cmeta[N];          // fx, fy, patch float-offset, pad
    __shared__ float4 cw[N];             // wx0, wx1, wy0/64, wy1/64
    __shared__ int    s_cnt;

    // ---- warp-0 prologue: params for 2 strokes per lane, ballot-compact ----
    if (tid < 32) {
        const int l = tid;
        const float2 br0 = ((const float2*)brushes)[b * N + l];
        const float2 br1 = ((const float2*)brushes)[b * N + l + 32];

        float mnx = fminf(br0.x, br1.x), mxx = fmaxf(br0.x, br1.x);
        float mny = fminf(br0.y, br1.y), mxy = fmaxf(br0.y, br1.y);
#pragma unroll
        for (int o = 16; o > 0; o >>= 1) {
            mnx = fminf(mnx, __shfl_xor_sync(0xffffffffu, mnx, o));
            mxx = fmaxf(mxx, __shfl_xor_sync(0xffffffffu, mxx, o));
            mny = fminf(mny, __shfl_xor_sync(0xffffffffu, mny, o));
            mxy = fmaxf(mxy, __shfl_xor_sync(0xffffffffu, mxy, o));
        }
        const float isx = 1.0f / (mxx - mnx + EPS) * (float)IMAGE_W;
        const float isy = 1.0f / (mxy - mny + EPS) * (float)IMAGE_H;

        int    fx[2], fy[2];
        float4 wt[2];
        bool   ov[2];
#pragma unroll
        for (int k = 0; k < 2; k++) {
            const float bx = k ? br1.x : br0.x;
            const float by = k ? br1.y : br0.y;
            const float axc = (bx - mnx) * isx - 15.5f;  // ux(q)=gx+q-15.5
            const float fx0f = floorf(axc);
            const float dx = axc - fx0f;
            const float ayc = (by - mny) * isy - 15.4f;  // uy(p)=gy+p-15.4
            const float fy0f = floorf(ayc);
            const float dy = ayc - fy0f;

            const float gx0 = __expf(-(dx * dx) / SIGMA2);
            const float gx1 = __expf(-((1.0f - dx) * (1.0f - dx)) / SIGMA2);
            const float wx0 = gx0 / (gx0 + gx1 + EPS);
            const float wx1 = gx1 / (gx0 + gx1 + EPS);

            const float gy0 = __expf(-(dy * dy) / SIGMA2);
            const float gy1 = __expf(-((1.0f - dy) * (1.0f - dy)) / SIGMA2);
            const float s  = 1.0f / 64.0f;               // fold /N into wy
            const float wy0 = gy0 / (gy0 + gy1 + EPS) * s;
            const float wy1 = gy1 / (gy0 + gy1 + EPS) * s;

            fx[k] = (int)fx0f;
            fy[k] = (int)fy0f;
            wt[k] = make_float4(wx0, wx1, wy0, wy1);
            ov[k] = !(fx[k] > tx0 + 31 || fx[k] + 32 < tx0 ||
                      fy[k] > ty0 + 31 || fy[k] + 32 < ty0);
        }

        const unsigned m0 = __ballot_sync(0xffffffffu, ov[0]);
        const unsigned m1 = __ballot_sync(0xffffffffu, ov[1]);
        const unsigned ltm = (1u << l) - 1u;
        const int base1 = __popc(m0);
        if (ov[0]) {
            const int pos = __popc(m0 & ltm);
            cmeta[pos] = make_int4(fx[0], fy[0], (b * N + l) * PSZ, 0);
            cw[pos]    = wt[0];
        }
        if (ov[1]) {
            const int pos = base1 + __popc(m1 & ltm);
            cmeta[pos] = make_int4(fx[1], fy[1], (b * N + l + 32) * PSZ, 0);
            cw[pos]    = wt[1];
        }
        if (l == 0) s_cnt = base1 + __popc(m1);
    }
    __syncthreads();
    const int cnt = s_cnt;

    // ---- gather ----
    const int lx    = tid & 31;
    const int g     = tid >> 5;          // 0..15
    const int x     = tx0 + lx;
    const int ybase = ty0 + g * 2;       // rows ybase, ybase+1

    float acc[C][2];
#pragma unroll
    for (int c = 0; c < C; c++) { acc[c][0] = 0.0f; acc[c][1] = 0.0f; }

#pragma unroll 2
    for (int s = 0; s < cnt; s++) {
        const int4   md = cmeta[s];
        const float4 wt = cw[s];
        const int i  = x - md.x;         // window col
        const int jb = ybase - md.y;     // window row of first output
        if (jb < -1 || jb > 32) continue;          // warp-uniform skip
        const bool c0 = ((unsigned)i       < 32u); // tap col i
        const bool c1 = ((unsigned)(i - 1) < 32u); // tap col i-1
        const float* Pn = patches + md.z + i;
#pragma unroll
        for (int c = 0; c < C; c++) {
            const float* Pc = Pn + c * (PH * PW);
            float h[3];
#pragma unroll
            for (int r = 0; r < 3; r++) {
                const int rr = jb - 1 + r;
                const bool rv = ((unsigned)rr < 32u);
                const float p0 = (rv & c0) ? __ldg(Pc + rr * PW)     : 0.0f;
                const float p1 = (rv & c1) ? __ldg(Pc + rr * PW - 1) : 0.0f;
                h[r] = wt.x * p0 + wt.y * p1;
            }
            acc[c][0] += wt.z * h[1] + wt.w * h[0];
            acc[c][1] += wt.z * h[2] + wt.w * h[1];
        }
    }

    // ---- coalesced stores: [b][c][y][x] ----
#pragma unroll
    for (int c = 0; c < C; c++) {
        float* oc = out + ((size_t)(b * C + c) * IMAGE_H) * IMAGE_W;
        oc[(size_t)(ybase    ) * IMAGE_W + x] = acc[c][0];
        oc[(size_t)(ybase + 1) * IMAGE_W + x] = acc[c][1];
    }
}

extern "C" void kernel_launch(void* const* d_in, const int* in_sizes, int n_in,
                              void* d_out, int out_size)
{
    const float* brushes = (const float*)d_in[0];   // [16,64,2]
    const float* patches = (const float*)d_in[1];   // [16,64,3,32,32]
    float* out = (float*)d_out;                     // [16,3,256,256]

    brush_kernel<<<B * 64, 512>>>(brushes, patches, out);
}